// round 14
// baseline (speedup 1.0000x reference)
#include <cuda_runtime.h>
#include <cuda_bf16.h>
#include <math.h>
#include <stdint.h>

#define N      4096
#define D      1024
#define TWO_N  8192

#define BM 128
#define BN 256
#define BK 64                   // 64 bf16 = 128 B per row chunk
#define NCHUNK (D / BK)         // 16
#define NBJ    (TWO_N / BN)     // 32 col blocks
#define NTILES (NBJ * (NBJ + 1))            // 1056 tiles: sum_{bj}(2bj+2)
#define STAGE_BYTES ((BM + BN) * 128)       // 49152
#define SMEM_RED_OFF (3 * STAGE_BYTES)      // 147456
#define SMEM_REQ (SMEM_RED_OFF + (BM + BN) * 4)

#define SWZ(off) ((off) ^ (((off) >> 3) & 0x70))

// ---------------- scratch (static device globals; no allocation) ----------------
__device__ __align__(1024) float          g_z [(size_t)TWO_N * D]; // fp32 normalized
__device__ __align__(1024) __nv_bfloat16  g_zb[(size_t)TWO_N * D]; // bf16 normalized
__device__ float g_denom[TWO_N];
__device__ float g_pos_sum, g_align_sum, g_u1, g_u2;

// ---------------- helpers -------------------------------------------------------
__device__ __forceinline__ uint32_t smem_u32(const void* p) {
    uint32_t a;
    asm("{ .reg .u64 t; cvta.to.shared.u64 t, %1; cvt.u32.u64 %0, t; }" : "=r"(a) : "l"(p));
    return a;
}

// FFMA-only exp2 (no MUFU). |t| <= ~15 here.
__device__ __forceinline__ float fexp2f(float t) {
    float zf = t + 12582912.0f;                 // 1.5*2^23 round-to-nearest-int
    int   e  = __float_as_int(zf) - 0x4B400000;
    float f  = t - (zf - 12582912.0f);          // f in [-0.5, 0.5]
    float p  = 1.33335581e-3f;
    p = fmaf(p, f, 9.61812911e-3f);
    p = fmaf(p, f, 5.55041086e-2f);
    p = fmaf(p, f, 2.40226507e-1f);
    p = fmaf(p, f, 6.93147182e-1f);
    p = fmaf(p, f, 1.0f);
    return __int_as_float(__float_as_int(p) + (e << 23));
}

// ---------------- normalize: fp32 + bf16 outputs (+ accumulator init) -----------
__global__ __launch_bounds__(256) void normalize_kernel(const float* __restrict__ p1,
                                                        const float* __restrict__ p2) {
    int row = blockIdx.x;
    if (threadIdx.x == 0) {
        g_denom[row] = 0.0f;
        if (row == 0) { g_pos_sum = 0.0f; g_align_sum = 0.0f; g_u1 = 0.0f; g_u2 = 0.0f; }
    }
    const float* src = (row < N) ? (p1 + (size_t)row * D)
                                 : (p2 + (size_t)(row - N) * D);
    float4 v = ((const float4*)src)[threadIdx.x];
    float s = v.x * v.x + v.y * v.y + v.z * v.z + v.w * v.w;

    __shared__ float red[256];
    red[threadIdx.x] = s;
    __syncthreads();
    #pragma unroll
    for (int st = 128; st > 0; st >>= 1) {
        if (threadIdx.x < st) red[threadIdx.x] += red[threadIdx.x + st];
        __syncthreads();
    }
    float inv = 1.0f / sqrtf(red[0]);
    float4 o;
    o.x = v.x * inv; o.y = v.y * inv; o.z = v.z * inv; o.w = v.w * inv;
    ((float4*)(g_z + (size_t)row * D))[threadIdx.x] = o;
    __nv_bfloat162 b0 = __floats2bfloat162_rn(o.x, o.y);
    __nv_bfloat162 b1 = __floats2bfloat162_rn(o.z, o.w);
    __nv_bfloat162* dst = (__nv_bfloat162*)(g_zb + (size_t)row * D);
    dst[threadIdx.x * 2]     = b0;
    dst[threadIdx.x * 2 + 1] = b1;
}

// ---------------- pos & align (fp32, exact) -------------------------------------
__global__ __launch_bounds__(256) void pos_kernel() {
    int i = blockIdx.x;
    float4 a = ((const float4*)(g_z + (size_t)i * D))[threadIdx.x];
    float4 b = ((const float4*)(g_z + (size_t)(N + i) * D))[threadIdx.x];
    float dot = a.x * b.x + a.y * b.y + a.z * b.z + a.w * b.w;
    float dx = a.x - b.x, dy = a.y - b.y, dz = a.z - b.z, dw = a.w - b.w;
    float sqd = dx * dx + dy * dy + dz * dz + dw * dw;

    __shared__ float r1[256], r2[256];
    r1[threadIdx.x] = dot;
    r2[threadIdx.x] = sqd;
    __syncthreads();
    #pragma unroll
    for (int st = 128; st > 0; st >>= 1) {
        if (threadIdx.x < st) {
            r1[threadIdx.x] += r1[threadIdx.x + st];
            r2[threadIdx.x] += r2[threadIdx.x + st];
        }
        __syncthreads();
    }
    if (threadIdx.x == 0) {
        atomicAdd(&g_pos_sum, r1[0]);
        atomicAdd(&g_align_sum, r2[0]);
    }
}

// ---------------- mma.sync bf16 sim GEMM: 128x256 tiles, strict-upper ----------
// 256 threads (8 warps, 2x4 grid of 64x64 warp tiles), 1 CTA/SM.
// Tiles (bi, bj) with bi <= 2*bj+1 intersect the strict upper triangle; the
// epilogue accumulates only elements with cg > rg, crediting denom[rg] (row)
// AND denom[cg] (col) -> each unordered pair counted exactly once.
__global__ void __launch_bounds__(256, 1) sim_kernel() {
    extern __shared__ __align__(128) char smem[];

    const int tid  = threadIdx.x;
    const int wid  = tid >> 5;
    const int lane = tid & 31;

    // decode: tiles before col-block bj = bj*(bj+1); bi = idx - bj*(bj+1).
    int idx = blockIdx.x;
    int bj = (int)((sqrtf(4.0f * (float)idx + 1.0f) - 1.0f) * 0.5f);
    if (bj > NBJ - 1) bj = NBJ - 1;
    if (bj < 0) bj = 0;
    while (bj > 0 && bj * (bj + 1) > idx) bj--;
    while ((bj + 1) * (bj + 2) <= idx) bj++;
    const int bi = idx - bj * (bj + 1);       // 0 .. 2*bj+1
    const int row0 = bi * BM;
    const int col0 = bj * BN;

    const int wm0  = (wid >> 2) * 64;   // 2x4 warp grid
    const int wn0  = (wid & 3) * 64;

    float* s_red  = (float*)(smem + SMEM_RED_OFF);          // row sums [128]
    float* s_redc = s_red + BM;                             // col sums [256]
    if (tid < BM) s_red[tid] = 0.0f;
    s_redc[tid] = 0.0f;

    const uint32_t sbase = smem_u32(smem);
    const char* zb = (const char*)g_zb;

    // stage one K chunk: 384 rows (A:128 then B:256) x 128B, swizzled.
    // 3072 sectors / 256 threads = 12 per thread.
    auto load_chunk = [&](int c) {
        uint32_t st = sbase + (uint32_t)(c % 3) * STAGE_BYTES;
        #pragma unroll
        for (int t = 0; t < 12; t++) {
            int idx2 = tid + t * 256;         // 0..3071
            int r    = idx2 >> 3;             // 0..383
            int ch   = idx2 & 7;              // 16B chunk in 128B row
            int lr, grow; uint32_t base;
            if (r < BM) { lr = r;      grow = row0 + lr; base = 0; }
            else        { lr = r - BM; grow = col0 + lr; base = BM * 128; }
            uint32_t dst = st + base + SWZ(lr * 128 + ch * 16);
            size_t srcoff = (size_t)grow * (D * 2) + (size_t)c * 128 + (size_t)ch * 16;
            asm volatile("cp.async.cg.shared.global [%0], [%1], 16;"
                         :: "r"(dst), "l"(__cvta_generic_to_global(zb + srcoff)) : "memory");
        }
        asm volatile("cp.async.commit_group;" ::: "memory");
    };

    float acc[4][8][4];                        // [mi][ni(n8)][frag]: 128 regs
    #pragma unroll
    for (int mi = 0; mi < 4; mi++)
        #pragma unroll
        for (int ni = 0; ni < 8; ni++)
            #pragma unroll
            for (int r = 0; r < 4; r++) acc[mi][ni][r] = 0.0f;

    load_chunk(0);
    load_chunk(1);

    for (int c = 0; c < NCHUNK; c++) {
        if (c + 2 < NCHUNK)
            asm volatile("cp.async.wait_group 1;" ::: "memory");
        else
            asm volatile("cp.async.wait_group 0;" ::: "memory");
        __syncthreads();                       // all warps done with chunk c-1
        if (c + 2 < NCHUNK) load_chunk(c + 2); // into buf (c-1)%3, provably free

        uint32_t stA = sbase + (uint32_t)(c % 3) * STAGE_BYTES;
        uint32_t stB = stA + BM * 128;

        #pragma unroll
        for (int ks = 0; ks < 4; ks++) {       // four k16 steps per 64-chunk
            uint32_t a[4][4], b[4][4];
            #pragma unroll
            for (int mi = 0; mi < 4; mi++) {
                uint32_t addr = stA + SWZ((wm0 + mi * 16 + (lane & 15)) * 128
                                          + ks * 32 + (lane >> 4) * 16);
                asm volatile("ldmatrix.sync.aligned.m8n8.x4.shared.b16 {%0,%1,%2,%3}, [%4];"
                             : "=r"(a[mi][0]), "=r"(a[mi][1]), "=r"(a[mi][2]), "=r"(a[mi][3])
                             : "r"(addr));
            }
            #pragma unroll
            for (int nb = 0; nb < 4; nb++) {   // 4 x4 loads cover 64 n (two n8 each)
                uint32_t addr = stB + SWZ((wn0 + nb * 16 + (lane & 15)) * 128
                                          + ks * 32 + (lane >> 4) * 16);
                asm volatile("ldmatrix.sync.aligned.m8n8.x4.shared.b16 {%0,%1,%2,%3}, [%4];"
                             : "=r"(b[nb][0]), "=r"(b[nb][1]), "=r"(b[nb][2]), "=r"(b[nb][3])
                             : "r"(addr));
            }
            #pragma unroll
            for (int mi = 0; mi < 4; mi++)
                #pragma unroll
                for (int ni = 0; ni < 8; ni++) {
                    int nb = ni >> 1, hi = ni & 1;  // frag {b[nb][hi], b[nb][hi+2]}
                    asm volatile(
                        "mma.sync.aligned.m16n8k16.row.col.f32.bf16.bf16.f32 "
                        "{%0,%1,%2,%3}, {%4,%5,%6,%7}, {%8,%9}, {%0,%1,%2,%3};"
                        : "+f"(acc[mi][ni][0]), "+f"(acc[mi][ni][1]),
                          "+f"(acc[mi][ni][2]), "+f"(acc[mi][ni][3])
                        : "r"(a[mi][0]), "r"(a[mi][1]), "r"(a[mi][2]), "r"(a[mi][3]),
                          "r"(b[nb][hi]), "r"(b[nb][hi + 2]));
                }
        }
    }

    // -------- epilogue: strict upper (cg > rg) only; row AND col sums; unif ----
    // unif regions align with tile boundaries: u1 = rows,cols in [0,2048);
    // u2 = rows,cols in [2048,4096).
    const bool u1 = (bi < 16) && (bj < 8);
    const bool u2 = (bi >= 16 && bi < 32) && (bj >= 8 && bj < 16);
    const bool ur = u1 || u2;
    float us = 0.0f;
    float cs[16];
    #pragma unroll
    for (int j = 0; j < 16; j++) cs[j] = 0.0f;

    #pragma unroll
    for (int mi = 0; mi < 4; mi++) {
        #pragma unroll
        for (int p = 0; p < 2; p++) {
            int rg = row0 + wm0 + mi * 16 + p * 8 + (lane >> 2);
            float rs = 0.0f;
            #pragma unroll
            for (int ni = 0; ni < 8; ni++) {
                #pragma unroll
                for (int q = 0; q < 2; q++) {
                    int cg = col0 + wn0 + ni * 8 + (lane & 3) * 2 + q;
                    if (cg > rg) {
                        float s = acc[mi][ni][p * 2 + q];
                        float e = fexp2f(s * 14.4269504089f);                    // exp(10 s)
                        rs += e;
                        cs[ni * 2 + q] += e;
                        if (ur) us += fexp2f(fmaf(s, 5.77078016356f, -5.77078016356f)); // exp(4s-4)
                    }
                }
            }
            rs += __shfl_xor_sync(0xffffffffu, rs, 1);
            rs += __shfl_xor_sync(0xffffffffu, rs, 2);
            if ((lane & 3) == 0)
                atomicAdd(&s_red[wm0 + mi * 16 + p * 8 + (lane >> 2)], rs);
        }
    }

    // column sums: reduce across the 8 row-lanes (lane bits 2..4)
    #pragma unroll
    for (int j = 0; j < 16; j++) {
        float v = cs[j];
        v += __shfl_xor_sync(0xffffffffu, v, 4);
        v += __shfl_xor_sync(0xffffffffu, v, 8);
        v += __shfl_xor_sync(0xffffffffu, v, 16);
        if (lane < 4)
            atomicAdd(&s_redc[wn0 + (j >> 1) * 8 + lane * 2 + (j & 1)], v);
    }

    if (ur) {
        #pragma unroll
        for (int o = 16; o > 0; o >>= 1)
            us += __shfl_down_sync(0xffffffffu, us, o);
        if (lane == 0)
            atomicAdd(u1 ? &g_u1 : &g_u2, 2.0f * us);   // each unordered pair once
    }
    __syncthreads();
    if (tid < BM) atomicAdd(&g_denom[row0 + tid], s_red[tid]);
    atomicAdd(&g_denom[col0 + tid], s_redc[tid]);
}

// ---------------- finalize ------------------------------------------------------
__global__ __launch_bounds__(256) void finalize_kernel(float* __restrict__ out) {
    __shared__ float red[256];
    float s = 0.0f;
    for (int i = threadIdx.x; i < TWO_N; i += 256)
        s += logf(g_denom[i]);
    red[threadIdx.x] = s;
    __syncthreads();
    #pragma unroll
    for (int st = 128; st > 0; st >>= 1) {
        if (threadIdx.x < st) red[threadIdx.x] += red[threadIdx.x + st];
        __syncthreads();
    }
    if (threadIdx.x == 0) {
        float loss = (red[0] - 20.0f * g_pos_sum) / (float)TWO_N;
        float lalign = g_align_sum / (float)N;
        const float npairs = 2048.0f * 2047.0f * 0.5f;
        float lunif = 0.5f * (logf(g_u1 * 0.5f / npairs) + logf(g_u2 * 0.5f / npairs));
        out[0] = loss;
        out[1] = lalign;
        out[2] = lunif;
    }
}

// ---------------- launch --------------------------------------------------------
extern "C" void kernel_launch(void* const* d_in, const int* in_sizes, int n_in,
                              void* d_out, int out_size) {
    const float* p1 = (const float*)d_in[0];
    const float* p2 = (const float*)d_in[1];
    float* out = (float*)d_out;

    cudaFuncSetAttribute(sim_kernel, cudaFuncAttributeMaxDynamicSharedMemorySize, SMEM_REQ);

    normalize_kernel<<<TWO_N, 256>>>(p1, p2);
    pos_kernel<<<N, 256>>>();
    sim_kernel<<<NTILES, 256, SMEM_REQ>>>();
    finalize_kernel<<<1, 256>>>(out);
}

// round 15
// speedup vs baseline: 1.2876x; 1.2876x over previous
#include <cuda_runtime.h>
#include <cuda_bf16.h>
#include <math.h>
#include <stdint.h>

#define N      4096
#define D      1024
#define TWO_N  8192

#define BM 128
#define BN 128
#define BK 64                   // 64 bf16 = 128 B per row chunk
#define NCHUNK (D / BK)         // 16
#define NB     (TWO_N / 128)    // 64 row/col blocks
#define NTILES (NB * (NB + 1) / 2)          // 2080 triangular tiles
#define STAGE_BYTES (BM * 128 + BN * 128)   // A + B per stage = 32768
#define SMEM_RED_OFF (3 * STAGE_BYTES)      // 98304
#define SMEM_REQ (SMEM_RED_OFF + 2 * BM * 4)

#define SWZ(off) ((off) ^ (((off) >> 3) & 0x70))

// ---------------- scratch (static device globals; no allocation) ----------------
__device__ __align__(1024) __nv_bfloat16  g_zb[(size_t)TWO_N * D]; // bf16 normalized
__device__ float g_denom[TWO_N];
__device__ float g_pos_sum, g_align_sum, g_u1, g_u2, g_logsum;

// ---------------- helpers -------------------------------------------------------
__device__ __forceinline__ uint32_t smem_u32(const void* p) {
    uint32_t a;
    asm("{ .reg .u64 t; cvta.to.shared.u64 t, %1; cvt.u32.u64 %0, t; }" : "=r"(a) : "l"(p));
    return a;
}

// FFMA-only exp2 (no MUFU). |t| <= ~15 here.
__device__ __forceinline__ float fexp2f(float t) {
    float zf = t + 12582912.0f;                 // 1.5*2^23 round-to-nearest-int
    int   e  = __float_as_int(zf) - 0x4B400000;
    float f  = t - (zf - 12582912.0f);          // f in [-0.5, 0.5]
    float p  = 1.33335581e-3f;
    p = fmaf(p, f, 9.61812911e-3f);
    p = fmaf(p, f, 5.55041086e-2f);
    p = fmaf(p, f, 2.40226507e-1f);
    p = fmaf(p, f, 6.93147182e-1f);
    p = fmaf(p, f, 1.0f);
    return __int_as_float(__float_as_int(p) + (e << 23));
}

// ---------------- fused init + normalize + pos/align ---------------------------
// One block per pair i: normalizes rows i and N+i, writes bf16 only,
// accumulates pos (dot) and align (||.||^2) inline, zeroes accumulators.
__global__ __launch_bounds__(256) void normalize_kernel(const float* __restrict__ p1,
                                                        const float* __restrict__ p2) {
    int i = blockIdx.x;                       // 0..N-1
    if (threadIdx.x == 0) {
        g_denom[i] = 0.0f;
        g_denom[N + i] = 0.0f;
        if (i == 0) {
            g_pos_sum = 0.0f; g_align_sum = 0.0f;
            g_u1 = 0.0f; g_u2 = 0.0f; g_logsum = 0.0f;
        }
    }
    float4 v1 = ((const float4*)(p1 + (size_t)i * D))[threadIdx.x];
    float4 v2 = ((const float4*)(p2 + (size_t)i * D))[threadIdx.x];
    float s1 = v1.x * v1.x + v1.y * v1.y + v1.z * v1.z + v1.w * v1.w;
    float s2 = v2.x * v2.x + v2.y * v2.y + v2.z * v2.z + v2.w * v2.w;

    __shared__ float r1[256], r2[256];
    r1[threadIdx.x] = s1;
    r2[threadIdx.x] = s2;
    __syncthreads();
    #pragma unroll
    for (int st = 128; st > 0; st >>= 1) {
        if (threadIdx.x < st) {
            r1[threadIdx.x] += r1[threadIdx.x + st];
            r2[threadIdx.x] += r2[threadIdx.x + st];
        }
        __syncthreads();
    }
    float inv1 = 1.0f / sqrtf(r1[0]);
    float inv2 = 1.0f / sqrtf(r2[0]);
    __syncthreads();                          // r1/r2 reuse below

    float4 o1, o2;
    o1.x = v1.x * inv1; o1.y = v1.y * inv1; o1.z = v1.z * inv1; o1.w = v1.w * inv1;
    o2.x = v2.x * inv2; o2.y = v2.y * inv2; o2.z = v2.z * inv2; o2.w = v2.w * inv2;

    __nv_bfloat162* d1 = (__nv_bfloat162*)(g_zb + (size_t)i * D);
    __nv_bfloat162* d2 = (__nv_bfloat162*)(g_zb + (size_t)(N + i) * D);
    d1[threadIdx.x * 2]     = __floats2bfloat162_rn(o1.x, o1.y);
    d1[threadIdx.x * 2 + 1] = __floats2bfloat162_rn(o1.z, o1.w);
    d2[threadIdx.x * 2]     = __floats2bfloat162_rn(o2.x, o2.y);
    d2[threadIdx.x * 2 + 1] = __floats2bfloat162_rn(o2.z, o2.w);

    float dot = o1.x * o2.x + o1.y * o2.y + o1.z * o2.z + o1.w * o2.w;
    float dx = o1.x - o2.x, dy = o1.y - o2.y, dz = o1.z - o2.z, dw = o1.w - o2.w;
    float sqd = dx * dx + dy * dy + dz * dz + dw * dw;

    r1[threadIdx.x] = dot;
    r2[threadIdx.x] = sqd;
    __syncthreads();
    #pragma unroll
    for (int st = 128; st > 0; st >>= 1) {
        if (threadIdx.x < st) {
            r1[threadIdx.x] += r1[threadIdx.x + st];
            r2[threadIdx.x] += r2[threadIdx.x + st];
        }
        __syncthreads();
    }
    if (threadIdx.x == 0) {
        atomicAdd(&g_pos_sum, r1[0]);
        atomicAdd(&g_align_sum, r2[0]);
    }
}

// ---------------- mma.sync bf16 sim GEMM: triangular, 64x64 warp tiles ----------
// (byte-identical mainloop/epilogue to the proven R13 kernel)
__global__ void __launch_bounds__(128, 2) sim_kernel() {
    extern __shared__ __align__(128) char smem[];

    const int tid  = threadIdx.x;
    const int wid  = tid >> 5;
    const int lane = tid & 31;

    // triangular decode: blockIdx.x -> (bi, bj), bi <= bj.
    int idx = blockIdx.x;
    int bi = (int)((129.0f - sqrtf(16641.0f - 8.0f * (float)idx)) * 0.5f);
    if (bi > NB - 1) bi = NB - 1;
    if (bi < 0) bi = 0;
    while (bi > 0 && bi * (129 - bi) / 2 > idx) bi--;
    while ((bi + 1) * (129 - (bi + 1)) / 2 <= idx) bi++;
    const int bj = bi + (idx - bi * (129 - bi) / 2);
    const int row0 = bi * BM;
    const int col0 = bj * BN;
    const bool diag = (bi == bj);

    const int wm0  = (wid >> 1) * 64;   // 2x2 warp grid
    const int wn0  = (wid & 1) * 64;

    float* s_red  = (float*)(smem + SMEM_RED_OFF);          // row sums [128]
    float* s_redc = s_red + BM;                             // col sums [128]
    if (tid < BM) { s_red[tid] = 0.0f; s_redc[tid] = 0.0f; }

    const uint32_t sbase = smem_u32(smem);
    const char* zb = (const char*)g_zb;

    auto load_chunk = [&](int c) {
        uint32_t st = sbase + (uint32_t)(c % 3) * STAGE_BYTES;
        #pragma unroll
        for (int t = 0; t < 16; t++) {
            int idx2 = tid + t * 128;         // 0..2047
            int r    = idx2 >> 3;             // 0..255
            int ch   = idx2 & 7;              // 16B chunk in 128B row
            int lr   = r & 127;
            int grow = (r < BM) ? (row0 + lr) : (col0 + lr);
            uint32_t dst = st + (uint32_t)(r < BM ? 0 : BM * 128) + SWZ(lr * 128 + ch * 16);
            size_t srcoff = (size_t)grow * (D * 2) + (size_t)c * 128 + (size_t)ch * 16;
            asm volatile("cp.async.cg.shared.global [%0], [%1], 16;"
                         :: "r"(dst), "l"(__cvta_generic_to_global(zb + srcoff)) : "memory");
        }
        asm volatile("cp.async.commit_group;" ::: "memory");
    };

    // fragment double buffers
    uint32_t afr[2][4][4], bfr[2][4][4];
    auto load_frags = [&](int ks, uint32_t stA, uint32_t stB, int buf) {
        #pragma unroll
        for (int mi = 0; mi < 4; mi++) {
            uint32_t addr = stA + SWZ((wm0 + mi * 16 + (lane & 15)) * 128
                                      + ks * 32 + (lane >> 4) * 16);
            asm volatile("ldmatrix.sync.aligned.m8n8.x4.shared.b16 {%0,%1,%2,%3}, [%4];"
                         : "=r"(afr[buf][mi][0]), "=r"(afr[buf][mi][1]),
                           "=r"(afr[buf][mi][2]), "=r"(afr[buf][mi][3])
                         : "r"(addr));
        }
        #pragma unroll
        for (int nb = 0; nb < 4; nb++) {
            uint32_t addr = stB + SWZ((wn0 + nb * 16 + (lane & 15)) * 128
                                      + ks * 32 + (lane >> 4) * 16);
            asm volatile("ldmatrix.sync.aligned.m8n8.x4.shared.b16 {%0,%1,%2,%3}, [%4];"
                         : "=r"(bfr[buf][nb][0]), "=r"(bfr[buf][nb][1]),
                           "=r"(bfr[buf][nb][2]), "=r"(bfr[buf][nb][3])
                         : "r"(addr));
        }
    };

    float acc[4][8][4];                        // [mi][ni(n8)][frag]: 128 regs
    #pragma unroll
    for (int mi = 0; mi < 4; mi++)
        #pragma unroll
        for (int ni = 0; ni < 8; ni++)
            #pragma unroll
            for (int r = 0; r < 4; r++) acc[mi][ni][r] = 0.0f;

    load_chunk(0);
    load_chunk(1);

    for (int c = 0; c < NCHUNK; c++) {
        if (c + 2 < NCHUNK)
            asm volatile("cp.async.wait_group 1;" ::: "memory");
        else
            asm volatile("cp.async.wait_group 0;" ::: "memory");
        __syncthreads();                       // all warps done with chunk c-1
        if (c + 2 < NCHUNK) load_chunk(c + 2); // into buf (c-1)%3, provably free

        uint32_t stA = sbase + (uint32_t)(c % 3) * STAGE_BYTES;
        uint32_t stB = stA + BM * 128;

        load_frags(0, stA, stB, 0);            // prime ks=0
        #pragma unroll
        for (int ks = 0; ks < 4; ks++) {       // four k16 steps per 64-chunk
            const int cur = ks & 1;
            if (ks < 3) load_frags(ks + 1, stA, stB, cur ^ 1);  // prefetch next ks
            #pragma unroll
            for (int mi = 0; mi < 4; mi++)
                #pragma unroll
                for (int ni = 0; ni < 8; ni++) {
                    int nb = ni >> 1, hi = ni & 1;  // frag {b[nb][hi], b[nb][hi+2]}
                    asm volatile(
                        "mma.sync.aligned.m16n8k16.row.col.f32.bf16.bf16.f32 "
                        "{%0,%1,%2,%3}, {%4,%5,%6,%7}, {%8,%9}, {%0,%1,%2,%3};"
                        : "+f"(acc[mi][ni][0]), "+f"(acc[mi][ni][1]),
                          "+f"(acc[mi][ni][2]), "+f"(acc[mi][ni][3])
                        : "r"(afr[cur][mi][0]), "r"(afr[cur][mi][1]),
                          "r"(afr[cur][mi][2]), "r"(afr[cur][mi][3]),
                          "r"(bfr[cur][nb][hi]), "r"(bfr[cur][nb][hi + 2]));
                }
        }
    }

    // -------- epilogue: exp, row sums, (off-diag: also col sums), unif ----------
    const bool u1 = (bi < 16) && (bj < 16);
    const bool u2 = (bi >= 16 && bi < 32) && (bj >= 16 && bj < 32);
    const bool ur = u1 || u2;
    float us = 0.0f;
    float cs[16];
    #pragma unroll
    for (int j = 0; j < 16; j++) cs[j] = 0.0f;

    #pragma unroll
    for (int mi = 0; mi < 4; mi++) {
        #pragma unroll
        for (int p = 0; p < 2; p++) {
            int rg = row0 + wm0 + mi * 16 + p * 8 + (lane >> 2);
            float rs = 0.0f;
            #pragma unroll
            for (int ni = 0; ni < 8; ni++) {
                #pragma unroll
                for (int q = 0; q < 2; q++) {
                    int cg = col0 + wn0 + ni * 8 + (lane & 3) * 2 + q;
                    float s = acc[mi][ni][p * 2 + q];
                    if (!(diag && cg == rg)) {
                        float e = fexp2f(s * 14.4269504089f);                    // exp(10 s)
                        rs += e;
                        cs[ni * 2 + q] += e;
                        if (ur) us += fexp2f(fmaf(s, 5.77078016356f, -5.77078016356f)); // exp(4s-4)
                    }
                }
            }
            rs += __shfl_xor_sync(0xffffffffu, rs, 1);
            rs += __shfl_xor_sync(0xffffffffu, rs, 2);
            if ((lane & 3) == 0)
                atomicAdd(&s_red[wm0 + mi * 16 + p * 8 + (lane >> 2)], rs);
        }
    }

    if (!diag) {
        #pragma unroll
        for (int j = 0; j < 16; j++) {
            float v = cs[j];
            v += __shfl_xor_sync(0xffffffffu, v, 4);
            v += __shfl_xor_sync(0xffffffffu, v, 8);
            v += __shfl_xor_sync(0xffffffffu, v, 16);
            if (lane < 4)
                atomicAdd(&s_redc[wn0 + (j >> 1) * 8 + lane * 2 + (j & 1)], v);
        }
    }

    if (ur) {
        #pragma unroll
        for (int o = 16; o > 0; o >>= 1)
            us += __shfl_down_sync(0xffffffffu, us, o);
        if (lane == 0)
            atomicAdd(u1 ? &g_u1 : &g_u2, diag ? us : 2.0f * us);
    }
    __syncthreads();
    if (tid < BM) {
        atomicAdd(&g_denom[row0 + tid], s_red[tid]);
        if (!diag) atomicAdd(&g_denom[col0 + tid], s_redc[tid]);
    }
}

// ---------------- parallel log partial reduction --------------------------------
__global__ __launch_bounds__(256) void logsum_kernel() {
    int gid = blockIdx.x * 256 + threadIdx.x;       // 32 blocks x 256 = 8192
    float s = logf(g_denom[gid]);
    __shared__ float red[256];
    red[threadIdx.x] = s;
    __syncthreads();
    #pragma unroll
    for (int st = 128; st > 0; st >>= 1) {
        if (threadIdx.x < st) red[threadIdx.x] += red[threadIdx.x + st];
        __syncthreads();
    }
    if (threadIdx.x == 0) atomicAdd(&g_logsum, red[0]);
}

// ---------------- writeout ------------------------------------------------------
__global__ void writeout_kernel(float* __restrict__ out) {
    float loss = (g_logsum - 20.0f * g_pos_sum) / (float)TWO_N;
    float lalign = g_align_sum / (float)N;
    const float npairs = 2048.0f * 2047.0f * 0.5f;
    float lunif = 0.5f * (logf(g_u1 * 0.5f / npairs) + logf(g_u2 * 0.5f / npairs));
    out[0] = loss;
    out[1] = lalign;
    out[2] = lunif;
}

// ---------------- launch --------------------------------------------------------
extern "C" void kernel_launch(void* const* d_in, const int* in_sizes, int n_in,
                              void* d_out, int out_size) {
    const float* p1 = (const float*)d_in[0];
    const float* p2 = (const float*)d_in[1];
    float* out = (float*)d_out;

    cudaFuncSetAttribute(sim_kernel, cudaFuncAttributeMaxDynamicSharedMemorySize, SMEM_REQ);

    normalize_kernel<<<N, 256>>>(p1, p2);
    sim_kernel<<<NTILES, 128, SMEM_REQ>>>();
    logsum_kernel<<<TWO_N / 256, 256>>>();
    writeout_kernel<<<1, 1>>>(out);
}